// round 5
// baseline (speedup 1.0000x reference)
#include <cuda_runtime.h>
#include <math.h>

#define BB 16
#define TT 2048
#define DD 1024
#define CC 6
#define NPART 32    // block-level partials per batch

// ---------------- device scratch (no allocs allowed) ----------------
__device__ int   g_tok[BB * TT];
__device__ float g_q[BB * DD];
__device__ float g_qk[BB * DD];
__device__ float g_xw[BB * DD];
__device__ float g_tmp[BB * DD];
__device__ float g_tmp2[BB * DD];
__device__ float g_pm[BB * NPART];
__device__ float g_pl[BB * NPART];
__device__ float g_pacc[BB * NPART * DD];   // 2 MB partial weighted sums

__device__ __forceinline__ float warp_sum(float v) {
#pragma unroll
    for (int o = 16; o > 0; o >>= 1) v += __shfl_down_sync(0xffffffffu, v, o);
    return v;
}
__device__ __forceinline__ float warp_allsum(float v) {
#pragma unroll
    for (int o = 16; o > 0; o >>= 1) v += __shfl_xor_sync(0xffffffffu, v, o);
    return v;
}
__device__ __forceinline__ float warp_allmax(float v) {
#pragma unroll
    for (int o = 16; o > 0; o >>= 1) v = fmaxf(v, __shfl_xor_sync(0xffffffffu, v, o));
    return v;
}

// ---------------- K1: detect layout (per-block, redundant) + convert; zero g_qk ----
__global__ void k_convert(const void* text, int V) {
    __shared__ int ok;
    if (threadIdx.x == 0) ok = 1;
    __syncthreads();
    const int2* t2 = (const int2*)text;
    // First 2048 int64-slots (16 KB) — in-bounds under both layouts.
    for (int i = threadIdx.x; i < 2048; i += blockDim.x) {
        int2 v = t2[i];
        if (v.y != 0 || v.x < 0 || v.x >= V) ok = 0;
    }
    __syncthreads();
    int is64 = ok;
    int i = blockIdx.x * blockDim.x + threadIdx.x;
    if (i < BB * TT) {
        int t;
        if (is64) t = (int)((const long long*)text)[i];
        else      t = ((const int*)text)[i];
        g_tok[i] = t;
    }
    if (i < BB * DD) g_qk[i] = 0.0f;
}

// ---------------- K2a: q[b] = Wq @ xlast[b] + bq  (grid = D) ----------------
__global__ void k_q(const float* __restrict__ emb, const float* __restrict__ Wq,
                    const float* __restrict__ bq) {
    int d = blockIdx.x, t = threadIdx.x;        // 256 threads
    float4 w4 = ((const float4*)(Wq + (size_t)d * DD))[t];
    float acc[BB];
#pragma unroll
    for (int b = 0; b < BB; b++) {
        int row = g_tok[(b + 1) * TT - 1];
        float4 x = ((const float4*)(emb + (size_t)row * DD))[t];
        acc[b] = w4.x * x.x + w4.y * x.y + w4.z * x.z + w4.w * x.w;
    }
    __shared__ float red[BB][9];
    int lane = t & 31, wid = t >> 5;
#pragma unroll
    for (int b = 0; b < BB; b++) {
        float r = warp_sum(acc[b]);
        if (lane == 0) red[b][wid] = r;
    }
    __syncthreads();
    if (t < BB) {
        float s = 0.f;
#pragma unroll
        for (int w = 0; w < 8; w++) s += red[t][w];
        g_q[t * DD + d] = s + bq[d];
    }
}

// ---------------- K2b: qk[b][:] += shq[b][d0..d0+8] * Wk[d0..d0+8][:]  (grid 128) -----
// Each thread owns 4 consecutive j (float4). 8 float4 W-loads, 512 FFMA, 64 atomics.
__global__ void k_qk(const float* __restrict__ Wk) {
    int t = threadIdx.x;
    int d0 = blockIdx.x * 8;
    __shared__ float shq[BB * 8];
    if (t < BB * 8) {
        int b = t >> 3, dd = t & 7;
        shq[t] = g_q[b * DD + d0 + dd];
    }
    __syncthreads();
    float4 w[8];
#pragma unroll
    for (int dd = 0; dd < 8; dd++)
        w[dd] = ((const float4*)(Wk + (size_t)(d0 + dd) * DD))[t];
#pragma unroll
    for (int half = 0; half < 2; half++) {
        float4 acc[8];
#pragma unroll
        for (int bb = 0; bb < 8; bb++) {
            int b = half * 8 + bb;
            float4 a = make_float4(0.f, 0.f, 0.f, 0.f);
#pragma unroll
            for (int dd = 0; dd < 8; dd++) {
                float q = shq[b * 8 + dd];
                a.x += q * w[dd].x; a.y += q * w[dd].y;
                a.z += q * w[dd].z; a.w += q * w[dd].w;
            }
            acc[bb] = a;
        }
#pragma unroll
        for (int bb = 0; bb < 8; bb++) {
            int b = half * 8 + bb;
            float* dst = &g_qk[b * DD + t * 4];
            atomicAdd(dst + 0, acc[bb].x); atomicAdd(dst + 1, acc[bb].y);
            atomicAdd(dst + 2, acc[bb].z); atomicAdd(dst + 3, acc[bb].w);
        }
    }
}

// ---------------- K3: fused scores+softmax+wsum, single pass over emb rows -----
// grid (32, BB), 256 threads (8 warps). Warp = 8 tokens; block partial = 64 tokens.
__global__ void __launch_bounds__(256) k_attn(const float* __restrict__ emb, float scale) {
    int b = blockIdx.y;
    int t = threadIdx.x, wid = t >> 5, lane = t & 31;
    __shared__ float4 shqk[256];
    __shared__ float sm[8], sl[8];
    __shared__ float4 sacc[8 * 256];            // 32 KB staging
    shqk[t] = ((const float4*)(g_qk + b * DD))[t];
    __syncthreads();
    float4 qv[8];
#pragma unroll
    for (int it = 0; it < 8; it++) qv[it] = shqk[it * 32 + lane];

    int j0 = b * TT + blockIdx.x * 64 + wid * 8;
    int rows[8];
#pragma unroll
    for (int jj = 0; jj < 8; jj++) rows[jj] = g_tok[j0 + jj];

    // ---- Stage A: 8 token dots, 64 independent loads, no cross-lane ops ----
    float dots[8];
#pragma unroll
    for (int jj = 0; jj < 8; jj++) dots[jj] = 0.f;
#pragma unroll
    for (int jj = 0; jj < 8; jj++) {
        const float4* e4 = (const float4*)(emb + (size_t)rows[jj] * DD);
#pragma unroll
        for (int it = 0; it < 8; it++) {
            float4 e = e4[it * 32 + lane];
            dots[jj] += e.x * qv[it].x + e.y * qv[it].y
                      + e.z * qv[it].z + e.w * qv[it].w;
        }
    }
#pragma unroll
    for (int jj = 0; jj < 8; jj++) dots[jj] = warp_allsum(dots[jj]) * scale;

    // ---- local softmax over 8 scores (lane-uniform) ----
    float m = dots[0];
#pragma unroll
    for (int jj = 1; jj < 8; jj++) m = fmaxf(m, dots[jj]);
    float pw[8], l = 0.f;
#pragma unroll
    for (int jj = 0; jj < 8; jj++) { pw[jj] = __expf(dots[jj] - m); l += pw[jj]; }

    // ---- Stage B: weighted sum; rows are L1/L2-hot ----
    float4 acc[8];
#pragma unroll
    for (int it = 0; it < 8; it++) acc[it] = make_float4(0.f, 0.f, 0.f, 0.f);
#pragma unroll
    for (int jj = 0; jj < 8; jj++) {
        float wgt = pw[jj];
        const float4* e4 = (const float4*)(emb + (size_t)rows[jj] * DD);
#pragma unroll
        for (int it = 0; it < 8; it++) {
            float4 e = e4[it * 32 + lane];
            acc[it].x += wgt * e.x; acc[it].y += wgt * e.y;
            acc[it].z += wgt * e.z; acc[it].w += wgt * e.w;
        }
    }

    // ---- block combine across 8 warps ----
    if (lane == 0) { sm[wid] = m; sl[wid] = l; }
    __syncthreads();
    float mB = sm[0];
#pragma unroll
    for (int w = 1; w < 8; w++) mB = fmaxf(mB, sm[w]);
    float f = __expf(m - mB);                  // lane-uniform per warp
#pragma unroll
    for (int it = 0; it < 8; it++) {
        float4 a = acc[it];
        sacc[wid * 256 + it * 32 + lane] =
            make_float4(a.x * f, a.y * f, a.z * f, a.w * f);
    }
    __syncthreads();
    float4 a = sacc[t];
#pragma unroll
    for (int w = 1; w < 8; w++) {
        float4 v = sacc[w * 256 + t];
        a.x += v.x; a.y += v.y; a.z += v.z; a.w += v.w;
    }
    int pidx = b * NPART + blockIdx.x;
    ((float4*)(g_pacc + (size_t)pidx * DD))[t] = a;
    if (t == 0) {
        float lB = 0.f;
#pragma unroll
        for (int w = 0; w < 8; w++) lB += sl[w] * __expf(sm[w] - mB);
        g_pm[pidx] = mB; g_pl[pidx] = lB;
    }
}

// ---------------- K4: combine 32 partials -> g_xw  (grid = BB, 256 thr) ----------
__global__ void k_attn2() {
    int b = blockIdx.x, t = threadIdx.x;
    __shared__ float swt[NPART];
    __shared__ float sLinv;
    if (t < 32) {
        float mi = g_pm[b * NPART + t];
        float li = g_pl[b * NPART + t];
        float M = warp_allmax(mi);
        float f = __expf(mi - M);
        float L = warp_allsum(li * f);
        swt[t] = f;
        if (t == 0) sLinv = 1.0f / L;
    }
    __syncthreads();
    float4 a = make_float4(0.f, 0.f, 0.f, 0.f);
    const float4* base = (const float4*)(g_pacc + (size_t)b * NPART * DD);
#pragma unroll 8
    for (int i = 0; i < NPART; i++) {
        float w = swt[i];
        float4 v = base[(size_t)i * (DD / 4) + t];
        a.x += w * v.x; a.y += w * v.y; a.z += w * v.z; a.w += w * v.w;
    }
    float li = sLinv;
    ((float4*)(g_xw + b * DD))[t] = make_float4(a.x * li, a.y * li, a.z * li, a.w * li);
}

// ---------------- K5: tmp[b] = Wv @ xw[b] + bv + xlast[b]  (grid = D) ----------------
__global__ void k_v(const float* __restrict__ emb, const float* __restrict__ Wv,
                    const float* __restrict__ bv) {
    int d = blockIdx.x, t = threadIdx.x;
    float4 w4 = ((const float4*)(Wv + (size_t)d * DD))[t];
    float acc[BB];
#pragma unroll
    for (int b = 0; b < BB; b++) {
        float4 x = ((const float4*)(g_xw + b * DD))[t];
        acc[b] = w4.x * x.x + w4.y * x.y + w4.z * x.z + w4.w * x.w;
    }
    __shared__ float red[BB][9];
    int lane = t & 31, wid = t >> 5;
#pragma unroll
    for (int b = 0; b < BB; b++) {
        float r = warp_sum(acc[b]);
        if (lane == 0) red[b][wid] = r;
    }
    __syncthreads();
    if (t < BB) {
        float s = 0.f;
#pragma unroll
        for (int w = 0; w < 8; w++) s += red[t][w];
        int row = g_tok[(t + 1) * TT - 1];
        g_tmp[t * DD + d] = s + bv[d] + emb[(size_t)row * DD + d];
    }
}

// ---------------- K6: tmp2[b] = y + Wfc @ y + bfc, y = tmp[b]/||tmp[b]|| -------
__global__ void k_fc(const float* __restrict__ Wfc, const float* __restrict__ bfc) {
    int d = blockIdx.x, t = threadIdx.x;
    float4 w4 = ((const float4*)(Wfc + (size_t)d * DD))[t];
    float acc[BB], ssq[BB];
#pragma unroll
    for (int b = 0; b < BB; b++) {
        float4 x = ((const float4*)(g_tmp + b * DD))[t];
        acc[b] = w4.x * x.x + w4.y * x.y + w4.z * x.z + w4.w * x.w;
        ssq[b] = x.x * x.x + x.y * x.y + x.z * x.z + x.w * x.w;
    }
    __shared__ float red[BB][9];
    __shared__ float red2[BB][9];
    int lane = t & 31, wid = t >> 5;
#pragma unroll
    for (int b = 0; b < BB; b++) {
        float r = warp_sum(acc[b]);
        float r2 = warp_sum(ssq[b]);
        if (lane == 0) { red[b][wid] = r; red2[b][wid] = r2; }
    }
    __syncthreads();
    if (t < BB) {
        float s = 0.f, ss = 0.f;
#pragma unroll
        for (int w = 0; w < 8; w++) { s += red[t][w]; ss += red2[t][w]; }
        float inv = 1.0f / fmaxf(sqrtf(ss), 1e-12f);
        g_tmp2[t * DD + d] = (g_tmp[t * DD + d] + s) * inv + bfc[d];
    }
}

// ---------------- K7: l2norm + sigmoid(Wo @ z + bo) ----------------
__global__ void k_out(const float* __restrict__ Wo, const float* __restrict__ bo,
                      float* __restrict__ out) {
    int b = blockIdx.x, t = threadIdx.x;
    float4 v = ((const float4*)(g_tmp2 + b * DD))[t];
    float ss = v.x * v.x + v.y * v.y + v.z * v.z + v.w * v.w;
    __shared__ float sh[256];
    __shared__ float inv2;
    sh[t] = ss; __syncthreads();
    for (int s = 128; s > 0; s >>= 1) { if (t < s) sh[t] += sh[t + s]; __syncthreads(); }
    if (t == 0) inv2 = 1.0f / fmaxf(sqrtf(sh[0]), 1e-12f);
    __syncthreads();
    int wid = t >> 5, lane = t & 31;
    if (wid < CC) {
        float a = 0.f;
        for (int k = lane; k < DD; k += 32)
            a += Wo[wid * DD + k] * g_tmp2[b * DD + k];
        a = warp_sum(a);
        if (lane == 0) {
            float logit = a * inv2 + bo[wid];
            out[b * CC + wid] = 1.0f / (1.0f + expf(-logit));
        }
    }
}

// ---------------- launch ----------------
extern "C" void kernel_launch(void* const* d_in, const int* in_sizes, int n_in,
                              void* d_out, int out_size) {
    const void*  text = d_in[0];
    const float* emb  = (const float*)d_in[2];
    const float* Wq   = (const float*)d_in[3];
    const float* bq   = (const float*)d_in[4];
    const float* Wk   = (const float*)d_in[5];
    const float* Wv   = (const float*)d_in[7];
    const float* bv   = (const float*)d_in[8];
    const float* Wfc  = (const float*)d_in[9];
    const float* bfc  = (const float*)d_in[10];
    const float* Wo   = (const float*)d_in[11];
    const float* bo   = (const float*)d_in[12];
    int V = in_sizes[2] / DD;

    k_convert<<<(BB * TT + 255) / 256, 256>>>(text, V);
    k_q<<<DD, 256>>>(emb, Wq, bq);
    k_qk<<<128, 256>>>(Wk);
    dim3 gat(NPART, BB);
    k_attn<<<gat, 256>>>(emb, 1.0f / 32.0f);
    k_attn2<<<BB, 256>>>();
    k_v<<<DD, 256>>>(emb, Wv, bv);
    k_fc<<<DD, 256>>>(Wfc, bfc);
    k_out<<<BB, 256>>>(Wo, bo, (float*)d_out);
}